// round 1
// baseline (speedup 1.0000x reference)
#include <cuda_runtime.h>
#include <cuda_bf16.h>
#include <mma.h>

using namespace nvcuda;

#define F 128
#define NN 50000
#define NE 800000
#define LDA 136   // bf16 elements per smem row (pad for bank spread; 136*2B rows, 16B-aligned)

// dynamic smem: Ahi + Alo tiles (bf16), reused as fp32 C tile in epilogue
#define SMEM_BYTES (2u * 128u * LDA * (unsigned)sizeof(__nv_bfloat16))  // 69632 >= 128*128*4

// ---------------- persistent device scratch ----------------
__device__ float g_P[(size_t)NN * F];   // node @ W1a_top + b1a
__device__ float g_S[(size_t)NN * F];   // segment_sum(relu(z))
__device__ float g_H[(size_t)NN * F];
__device__ float g_T[(size_t)NN * F];
__device__ float g_deg[NN];

__device__ __nv_bfloat16 g_w1at_hi[F*F], g_w1at_lo[F*F];
__device__ __nv_bfloat16 g_w1ab_hi[F*F], g_w1ab_lo[F*F];
__device__ __nv_bfloat16 g_w1b_hi [F*F], g_w1b_lo [F*F];
__device__ __nv_bfloat16 g_w2a_hi [F*F], g_w2a_lo [F*F];
__device__ __nv_bfloat16 g_w2b_hi [F*F], g_w2b_lo [F*F];

// ---------------- helpers ----------------
__device__ __forceinline__ void splitf(float x, __nv_bfloat16* hi, __nv_bfloat16* lo) {
    __nv_bfloat16 h = __float2bfloat16(x);            // RN
    *hi = h;
    *lo = __float2bfloat16(x - __bfloat162float(h));  // residual, also RN (error ~2^-18 |x|)
}

__global__ void prep_kernel(const float* __restrict__ W1a, const float* __restrict__ W1b,
                            const float* __restrict__ W2a, const float* __restrict__ W2b) {
    int i = blockIdx.x * blockDim.x + threadIdx.x;
    if (i < F * F) {
        splitf(W1a[i],          &g_w1at_hi[i], &g_w1at_lo[i]);   // rows 0..127 of W1a
        splitf(W1a[F * F + i],  &g_w1ab_hi[i], &g_w1ab_lo[i]);   // rows 128..255
        splitf(W1b[i],          &g_w1b_hi[i],  &g_w1b_lo[i]);
        splitf(W2a[i],          &g_w2a_hi[i],  &g_w2a_lo[i]);
        splitf(W2b[i],          &g_w2b_hi[i],  &g_w2b_lo[i]);
    }
}

__global__ void zero_kernel() {
    size_t stride = (size_t)gridDim.x * blockDim.x;
    size_t gid = (size_t)blockIdx.x * blockDim.x + threadIdx.x;
    float4 z = make_float4(0.f, 0.f, 0.f, 0.f);
    float4* S4 = reinterpret_cast<float4*>(g_S);
    for (size_t i = gid; i < (size_t)NN * F / 4; i += stride) S4[i] = z;
    for (size_t i = gid; i < (size_t)NN; i += stride) g_deg[i] = 0.f;
}

// load 128x128 fp32 tile -> split into bf16 hi/lo in smem
__device__ __forceinline__ void load_split_tile(const float* __restrict__ A, int row0, int M,
                                                __nv_bfloat16* Ahi, __nv_bfloat16* Alo) {
    for (int i = threadIdx.x; i < 128 * 32; i += blockDim.x) {
        int r = i >> 5;
        int c = (i & 31) << 2;
        float4 v;
        int gr = row0 + r;
        if (gr < M) v = *reinterpret_cast<const float4*>(A + (size_t)gr * F + c);
        else        v = make_float4(0.f, 0.f, 0.f, 0.f);
        __nv_bfloat16 h, l;
        splitf(v.x, &h, &l); Ahi[r*LDA + c + 0] = h; Alo[r*LDA + c + 0] = l;
        splitf(v.y, &h, &l); Ahi[r*LDA + c + 1] = h; Alo[r*LDA + c + 1] = l;
        splitf(v.z, &h, &l); Ahi[r*LDA + c + 2] = h; Alo[r*LDA + c + 2] = l;
        splitf(v.w, &h, &l); Ahi[r*LDA + c + 3] = h; Alo[r*LDA + c + 3] = l;
    }
    __syncthreads();
}

// 128x128x128 GEMM with bf16x3 precision recovery; result -> Cs (fp32, ld=128)
// 8 warps; warp w owns rows [w*16, w*16+16) x all 128 cols (8 accumulator tiles)
__device__ __forceinline__ void tile_gemm(const __nv_bfloat16* Ahi, const __nv_bfloat16* Alo,
                                          const __nv_bfloat16* __restrict__ Whi,
                                          const __nv_bfloat16* __restrict__ Wlo,
                                          float* Cs) {
    int w = threadIdx.x >> 5;
    wmma::fragment<wmma::accumulator, 16, 16, 16, float> acc[8];
#pragma unroll
    for (int j = 0; j < 8; j++) wmma::fill_fragment(acc[j], 0.f);

#pragma unroll 1
    for (int k = 0; k < F; k += 16) {
        wmma::fragment<wmma::matrix_a, 16, 16, 16, __nv_bfloat16, wmma::row_major> ahi, alo;
        wmma::load_matrix_sync(ahi, Ahi + (w * 16) * LDA + k, LDA);
        wmma::load_matrix_sync(alo, Alo + (w * 16) * LDA + k, LDA);
#pragma unroll
        for (int j = 0; j < 8; j++) {
            wmma::fragment<wmma::matrix_b, 16, 16, 16, __nv_bfloat16, wmma::row_major> bhi, blo;
            wmma::load_matrix_sync(bhi, Whi + k * F + j * 16, F);   // L1/L2-resident weights
            wmma::load_matrix_sync(blo, Wlo + k * F + j * 16, F);
            wmma::mma_sync(acc[j], ahi, bhi, acc[j]);
            wmma::mma_sync(acc[j], alo, bhi, acc[j]);
            wmma::mma_sync(acc[j], ahi, blo, acc[j]);
        }
    }
    __syncthreads();   // done with A smem; Cs aliases it
#pragma unroll
    for (int j = 0; j < 8; j++)
        wmma::store_matrix_sync(Cs + (w * 16) * F + j * 16, acc[j], F, wmma::mem_row_major);
    __syncthreads();
}

// ---------------- node-side GEMM: out = act(A@W + rowscale*bias + residual) ----------------
__global__ void gemm_node(const float* __restrict__ A, int M, int wsel,
                          const float* __restrict__ bias,
                          const float* __restrict__ rowscale,
                          const float* __restrict__ residual,
                          int do_relu,
                          float* __restrict__ out) {
    extern __shared__ char smem[];
    __nv_bfloat16* Ahi = reinterpret_cast<__nv_bfloat16*>(smem);
    __nv_bfloat16* Alo = Ahi + 128 * LDA;
    float* Cs = reinterpret_cast<float*>(smem);

    const __nv_bfloat16 *Whi, *Wlo;
    switch (wsel) {
        case 0:  Whi = g_w1at_hi; Wlo = g_w1at_lo; break;
        case 1:  Whi = g_w1b_hi;  Wlo = g_w1b_lo;  break;
        case 2:  Whi = g_w2a_hi;  Wlo = g_w2a_lo;  break;
        default: Whi = g_w2b_hi;  Wlo = g_w2b_lo;  break;
    }

    int row0 = blockIdx.x * 128;
    load_split_tile(A, row0, M, Ahi, Alo);
    tile_gemm(Ahi, Alo, Whi, Wlo, Cs);

    for (int i = threadIdx.x; i < 128 * 32; i += blockDim.x) {
        int r = i >> 5;
        int c = (i & 31) << 2;
        int gr = row0 + r;
        if (gr >= M) continue;
        float4 v = *reinterpret_cast<float4*>(Cs + r * F + c);
        float rs = rowscale ? rowscale[gr] : 1.f;
        v.x += rs * bias[c + 0];
        v.y += rs * bias[c + 1];
        v.z += rs * bias[c + 2];
        v.w += rs * bias[c + 3];
        if (residual) {
            const float4 q = *reinterpret_cast<const float4*>(residual + (size_t)gr * F + c);
            v.x += q.x; v.y += q.y; v.z += q.z; v.w += q.w;
        }
        if (do_relu) {
            v.x = fmaxf(v.x, 0.f); v.y = fmaxf(v.y, 0.f);
            v.z = fmaxf(v.z, 0.f); v.w = fmaxf(v.w, 0.f);
        }
        *reinterpret_cast<float4*>(out + (size_t)gr * F + c) = v;
    }
}

// ---------------- edge kernel: Q = E@W1a_bot; r = relu(Q + P[src]); scatter-add r into S[dst] ----------------
__global__ void edge_kernel(const float* __restrict__ Efeat,
                            const int* __restrict__ src,
                            const int* __restrict__ dst) {
    extern __shared__ char smem[];
    __nv_bfloat16* Ahi = reinterpret_cast<__nv_bfloat16*>(smem);
    __nv_bfloat16* Alo = Ahi + 128 * LDA;
    float* Cs = reinterpret_cast<float*>(smem);

    int row0 = blockIdx.x * 128;       // NE is an exact multiple of 128
    load_split_tile(Efeat, row0, NE, Ahi, Alo);
    tile_gemm(Ahi, Alo, g_w1ab_hi, g_w1ab_lo, Cs);

    for (int i = threadIdx.x; i < 128 * 32; i += blockDim.x) {
        int r = i >> 5;
        int c = (i & 31) << 2;
        int e = row0 + r;
        int s = src[e];
        int d = dst[e];
        float4 v = *reinterpret_cast<float4*>(Cs + r * F + c);
        const float4 p = *reinterpret_cast<const float4*>(g_P + (size_t)s * F + c);
        v.x = fmaxf(v.x + p.x, 0.f);
        v.y = fmaxf(v.y + p.y, 0.f);
        v.z = fmaxf(v.z + p.z, 0.f);
        v.w = fmaxf(v.w + p.w, 0.f);
        float* addr = g_S + (size_t)d * F + c;
        asm volatile("red.global.add.v4.f32 [%0], {%1,%2,%3,%4};"
                     :: "l"(addr), "f"(v.x), "f"(v.y), "f"(v.z), "f"(v.w)
                     : "memory");
    }
    if (threadIdx.x < 128)
        atomicAdd(&g_deg[dst[row0 + threadIdx.x]], 1.0f);
}

// ---------------- launch ----------------
extern "C" void kernel_launch(void* const* d_in, const int* in_sizes, int n_in,
                              void* d_out, int out_size) {
    const float* node  = (const float*)d_in[0];
    const float* edgef = (const float*)d_in[1];
    const int*   src   = (const int*)  d_in[2];
    const int*   dst   = (const int*)  d_in[3];
    const float* W1a   = (const float*)d_in[4];
    const float* b1a   = (const float*)d_in[5];
    const float* W1b   = (const float*)d_in[6];
    const float* b1b   = (const float*)d_in[7];
    const float* W2a   = (const float*)d_in[8];
    const float* b2a   = (const float*)d_in[9];
    const float* W2b   = (const float*)d_in[10];
    const float* b2b   = (const float*)d_in[11];
    float* out = (float*)d_out;

    cudaFuncSetAttribute(gemm_node,   cudaFuncAttributeMaxDynamicSharedMemorySize, (int)SMEM_BYTES);
    cudaFuncSetAttribute(edge_kernel, cudaFuncAttributeMaxDynamicSharedMemorySize, (int)SMEM_BYTES);

    float *P, *S, *H, *T, *deg;
    cudaGetSymbolAddress((void**)&P,   g_P);
    cudaGetSymbolAddress((void**)&S,   g_S);
    cudaGetSymbolAddress((void**)&H,   g_H);
    cudaGetSymbolAddress((void**)&T,   g_T);
    cudaGetSymbolAddress((void**)&deg, g_deg);

    const int nodeBlocks = (NN + 127) / 128;

    prep_kernel<<<64, 256>>>(W1a, W1b, W2a, W2b);
    zero_kernel<<<512, 256>>>();
    // P = node @ W1a_top + b1a
    gemm_node<<<nodeBlocks, 256, SMEM_BYTES>>>(node, NN, 0, b1a, nullptr, nullptr, 0, P);
    // per-edge: relu(E@W1a_bot + P[src]) scatter-added into S[dst]; deg counts
    edge_kernel<<<NE / 128, 256, SMEM_BYTES>>>(edgef, src, dst);
    // H = S @ W1b + deg*b1b + node_feats
    gemm_node<<<nodeBlocks, 256, SMEM_BYTES>>>(S, NN, 1, b1b, deg, node, 0, H);
    // T = relu(H @ W2a + b2a)
    gemm_node<<<nodeBlocks, 256, SMEM_BYTES>>>(H, NN, 2, b2a, nullptr, nullptr, 1, T);
    // out = T @ W2b + b2b
    gemm_node<<<nodeBlocks, 256, SMEM_BYTES>>>(T, NN, 3, b2b, nullptr, nullptr, 0, out);
}

// round 3
// speedup vs baseline: 2.2047x; 2.2047x over previous
#include <cuda_runtime.h>
#include <cuda_bf16.h>
#include <cstdint>

#define F 128
#define NN 50000
#define NE 800000

#define LDA 136            // bf16 elems per smem row (pad: conflict-free ldmatrix)
#define LDC 132            // fp32 elems per Cs row

// ---- smem layout (bytes) ----
#define OFF_AHI 0u
#define OFF_ALO 34816u     // 128*136*2
#define OFF_BHI 69632u
#define OFF_BLO 104448u
#define SMEM_REQ 139264u
// Cs (fp32 128 x LDC = 67584 B) aliases the A region [0, 69632)

// ---------------- persistent device scratch ----------------
__device__ float g_P[(size_t)NN * F];
__device__ float g_S[(size_t)NN * F];
__device__ float g_H[(size_t)NN * F];
__device__ float g_T[(size_t)NN * F];
__device__ float g_deg[NN];

// ---------------- low-level helpers ----------------
__device__ __forceinline__ uint32_t cvta_smem(const void* p) {
    uint32_t a;
    asm("{ .reg .u64 t; cvta.to.shared.u64 t, %1; cvt.u32.u64 %0, t; }" : "=r"(a) : "l"(p));
    return a;
}

__device__ __forceinline__ void ldsm4(uint32_t addr, uint32_t& r0, uint32_t& r1,
                                      uint32_t& r2, uint32_t& r3) {
    asm volatile("ldmatrix.sync.aligned.m8n8.x4.shared.b16 {%0,%1,%2,%3}, [%4];"
                 : "=r"(r0), "=r"(r1), "=r"(r2), "=r"(r3) : "r"(addr));
}

__device__ __forceinline__ void mma_bf16(float* c, uint32_t a0, uint32_t a1, uint32_t a2,
                                         uint32_t a3, uint32_t b0, uint32_t b1) {
    asm volatile("mma.sync.aligned.m16n8k16.row.col.f32.bf16.bf16.f32 "
                 "{%0,%1,%2,%3}, {%4,%5,%6,%7}, {%8,%9}, {%0,%1,%2,%3};"
                 : "+f"(c[0]), "+f"(c[1]), "+f"(c[2]), "+f"(c[3])
                 : "r"(a0), "r"(a1), "r"(a2), "r"(a3), "r"(b0), "r"(b1));
}

__device__ __forceinline__ void splitf(float x, __nv_bfloat16* hi, __nv_bfloat16* lo) {
    __nv_bfloat16 h = __float2bfloat16(x);
    *hi = h;
    *lo = __float2bfloat16(x - __bfloat162float(h));
}

__global__ void zero_kernel() {
    size_t stride = (size_t)gridDim.x * blockDim.x;
    size_t gid = (size_t)blockIdx.x * blockDim.x + threadIdx.x;
    float4 z = make_float4(0.f, 0.f, 0.f, 0.f);
    float4* S4 = reinterpret_cast<float4*>(g_S);
    for (size_t i = gid; i < (size_t)NN * F / 4; i += stride) S4[i] = z;
    for (size_t i = gid; i < (size_t)NN; i += stride) g_deg[i] = 0.f;
}

// ---------------- persistent fused GEMM ----------------
// is_edge=1: epilogue = relu(z + P[src]) scatter-added into S[dst], deg counts
// is_edge=0: out = act(z + rowscale*bias + residual)
__global__ void __launch_bounds__(256, 1)
gnn_gemm(const float* __restrict__ A, const float* __restrict__ Wg,
         const float* __restrict__ bias, const float* __restrict__ rowscale,
         const float* __restrict__ residual, float* __restrict__ outp,
         const int* __restrict__ src, const int* __restrict__ dst,
         int M, int ntiles, int do_relu, int is_edge) {
    extern __shared__ char sm[];
    const uint32_t sb = cvta_smem(sm);
    const int tid = threadIdx.x;

    // ---- stage weights once: B^T[n][k] = Wg[k][n], split hi/lo ----
    {
        const float4* W4 = reinterpret_cast<const float4*>(Wg);
        for (int idx = tid; idx < F * F / 4; idx += 256) {
            int k = idx >> 5;
            int n0 = (idx & 31) << 2;
            float4 wv = __ldg(W4 + idx);
#pragma unroll
            for (int j = 0; j < 4; j++) {
                __nv_bfloat16 h, l;
                splitf((&wv.x)[j], &h, &l);
                uint32_t o = (uint32_t)((n0 + j) * LDA + k) * 2u;
                *reinterpret_cast<__nv_bfloat16*>(sm + OFF_BHI + o) = h;
                *reinterpret_cast<__nv_bfloat16*>(sm + OFF_BLO + o) = l;
            }
        }
    }

    const int w = tid >> 5, lane = tid & 31;
    const int wr = w >> 2, wc = w & 3;          // warp tile: rows wr*64.., cols wc*32..
    const int g = lane >> 2, t = lane & 3;

    // per-lane ldmatrix base element-offsets (in bf16 elems)
    const uint32_t uA = (uint32_t)((wr * 64 + ((lane >> 3) & 1) * 8 + (lane & 7)) * LDA
                                   + (lane >> 4) * 8);
    const uint32_t uB = (uint32_t)((wc * 32 + (lane >> 4) * 8 + (lane & 7)) * LDA
                                   + ((lane >> 3) & 1) * 8);

    float* Cs = reinterpret_cast<float*>(sm);   // aliases A region

    for (int tile = blockIdx.x; tile < ntiles; tile += gridDim.x) {
        const int row0 = tile * 128;

        // ---- load & split A tile ----
        for (int idx = tid; idx < 4096; idx += 256) {
            int r = idx >> 5;
            int c4 = (idx & 31) << 2;
            int gr = row0 + r;
            float4 v = make_float4(0.f, 0.f, 0.f, 0.f);
            if (gr < M) v = __ldg(reinterpret_cast<const float4*>(A + (size_t)gr * F + c4));
            __nv_bfloat16 h0, l0, h1, l1, h2, l2, h3, l3;
            splitf(v.x, &h0, &l0); splitf(v.y, &h1, &l1);
            splitf(v.z, &h2, &l2); splitf(v.w, &h3, &l3);
            uint32_t o = (uint32_t)(r * LDA + c4) * 2u;
            __nv_bfloat162 p0; p0.x = h0; p0.y = h1;
            __nv_bfloat162 p1; p1.x = h2; p1.y = h3;
            __nv_bfloat162 q0; q0.x = l0; q0.y = l1;
            __nv_bfloat162 q1; q1.x = l2; q1.y = l3;
            *reinterpret_cast<__nv_bfloat162*>(sm + OFF_AHI + o)     = p0;
            *reinterpret_cast<__nv_bfloat162*>(sm + OFF_AHI + o + 4) = p1;
            *reinterpret_cast<__nv_bfloat162*>(sm + OFF_ALO + o)     = q0;
            *reinterpret_cast<__nv_bfloat162*>(sm + OFF_ALO + o + 4) = q1;
        }
        __syncthreads();

        // ---- 128x128x128 bf16x3 GEMM, acc in registers ----
        float acc[4][4][4];
#pragma unroll
        for (int mt = 0; mt < 4; mt++)
#pragma unroll
            for (int nt = 0; nt < 4; nt++)
#pragma unroll
                for (int i = 0; i < 4; i++) acc[mt][nt][i] = 0.f;

#pragma unroll
        for (int ks = 0; ks < 8; ks++) {
            const uint32_t kofs = (uint32_t)(ks * 16) * 2u;
            uint32_t ah[4][4], al[4][4];
#pragma unroll
            for (int mt = 0; mt < 4; mt++) {
                uint32_t ao = (uA + (uint32_t)(mt * 16 * LDA)) * 2u + kofs;
                ldsm4(sb + OFF_AHI + ao, ah[mt][0], ah[mt][1], ah[mt][2], ah[mt][3]);
                ldsm4(sb + OFF_ALO + ao, al[mt][0], al[mt][1], al[mt][2], al[mt][3]);
            }
            uint32_t bh[4][2], bl[4][2];
#pragma unroll
            for (int np = 0; np < 2; np++) {
                uint32_t bo = (uB + (uint32_t)(np * 16 * LDA)) * 2u + kofs;
                ldsm4(sb + OFF_BHI + bo, bh[2*np][0], bh[2*np][1], bh[2*np+1][0], bh[2*np+1][1]);
                ldsm4(sb + OFF_BLO + bo, bl[2*np][0], bl[2*np][1], bl[2*np+1][0], bl[2*np+1][1]);
            }
#pragma unroll
            for (int mt = 0; mt < 4; mt++)
#pragma unroll
                for (int nt = 0; nt < 4; nt++) {
                    mma_bf16(acc[mt][nt], ah[mt][0], ah[mt][1], ah[mt][2], ah[mt][3],
                             bh[nt][0], bh[nt][1]);
                    mma_bf16(acc[mt][nt], al[mt][0], al[mt][1], al[mt][2], al[mt][3],
                             bh[nt][0], bh[nt][1]);
                    mma_bf16(acc[mt][nt], ah[mt][0], ah[mt][1], ah[mt][2], ah[mt][3],
                             bl[nt][0], bl[nt][1]);
                }
        }
        __syncthreads();   // done reading A smem; reuse as Cs

        // ---- spill acc to Cs ----
#pragma unroll
        for (int mt = 0; mt < 4; mt++) {
            const int r0 = wr * 64 + mt * 16 + g;
#pragma unroll
            for (int nt = 0; nt < 4; nt++) {
                const int c0 = wc * 32 + nt * 8 + 2 * t;
                *reinterpret_cast<float2*>(Cs + r0 * LDC + c0) =
                    make_float2(acc[mt][nt][0], acc[mt][nt][1]);
                *reinterpret_cast<float2*>(Cs + (r0 + 8) * LDC + c0) =
                    make_float2(acc[mt][nt][2], acc[mt][nt][3]);
            }
        }
        __syncthreads();

        // ---- epilogue ----
        if (is_edge) {
            for (int idx = tid; idx < 4096; idx += 256) {
                int r = idx >> 5;
                int c = (idx & 31) << 2;
                int e = row0 + r;
                int s = __ldg(src + e);
                int d = __ldg(dst + e);
                float4 v = *reinterpret_cast<float4*>(Cs + r * LDC + c);
                float4 p = __ldg(reinterpret_cast<const float4*>(g_P + (size_t)s * F + c));
                v.x = fmaxf(v.x + p.x, 0.f);
                v.y = fmaxf(v.y + p.y, 0.f);
                v.z = fmaxf(v.z + p.z, 0.f);
                v.w = fmaxf(v.w + p.w, 0.f);
                float* addr = g_S + (size_t)d * F + c;
                asm volatile("red.global.add.v4.f32 [%0], {%1,%2,%3,%4};"
                             :: "l"(addr), "f"(v.x), "f"(v.y), "f"(v.z), "f"(v.w)
                             : "memory");
            }
            if (tid < 128) atomicAdd(&g_deg[__ldg(dst + row0 + tid)], 1.0f);
        } else {
            for (int idx = tid; idx < 4096; idx += 256) {
                int r = idx >> 5;
                int c = (idx & 31) << 2;
                int gr = row0 + r;
                if (gr >= M) continue;
                float4 v = *reinterpret_cast<float4*>(Cs + r * LDC + c);
                float4 bb = __ldg(reinterpret_cast<const float4*>(bias + c));
                float rs = rowscale ? __ldg(rowscale + gr) : 1.f;
                v.x += rs * bb.x; v.y += rs * bb.y; v.z += rs * bb.z; v.w += rs * bb.w;
                if (residual) {
                    float4 q = __ldg(reinterpret_cast<const float4*>(residual + (size_t)gr * F + c));
                    v.x += q.x; v.y += q.y; v.z += q.z; v.w += q.w;
                }
                if (do_relu) {
                    v.x = fmaxf(v.x, 0.f); v.y = fmaxf(v.y, 0.f);
                    v.z = fmaxf(v.z, 0.f); v.w = fmaxf(v.w, 0.f);
                }
                *reinterpret_cast<float4*>(outp + (size_t)gr * F + c) = v;
            }
        }
        __syncthreads();   // Cs reads complete before next tile overwrites A region
    }
}

// ---------------- launch ----------------
extern "C" void kernel_launch(void* const* d_in, const int* in_sizes, int n_in,
                              void* d_out, int out_size) {
    const float* node  = (const float*)d_in[0];
    const float* edgef = (const float*)d_in[1];
    const int*   src   = (const int*)  d_in[2];
    const int*   dst   = (const int*)  d_in[3];
    const float* W1a   = (const float*)d_in[4];
    const float* b1a   = (const float*)d_in[5];
    const float* W1b   = (const float*)d_in[6];
    const float* b1b   = (const float*)d_in[7];
    const float* W2a   = (const float*)d_in[8];
    const float* b2a   = (const float*)d_in[9];
    const float* W2b   = (const float*)d_in[10];
    const float* b2b   = (const float*)d_in[11];
    float* out = (float*)d_out;

    cudaFuncSetAttribute(gnn_gemm, cudaFuncAttributeMaxDynamicSharedMemorySize, (int)SMEM_REQ);

    float *P, *S, *H, *T, *deg;
    cudaGetSymbolAddress((void**)&P,   g_P);
    cudaGetSymbolAddress((void**)&S,   g_S);
    cudaGetSymbolAddress((void**)&H,   g_H);
    cudaGetSymbolAddress((void**)&T,   g_T);
    cudaGetSymbolAddress((void**)&deg, g_deg);

    const int nodeTiles = (NN + 127) / 128;   // 391
    const int edgeTiles = NE / 128;           // 6250
    const int GRID = 148;

    zero_kernel<<<512, 256>>>();
    // P = node @ W1a_top + b1a   (bias folded in the H step? no: fold b1a here via bias path)
    gnn_gemm<<<GRID, 256, SMEM_REQ>>>(node, W1a, b1a, nullptr, nullptr, P,
                                      nullptr, nullptr, NN, nodeTiles, 0, 0);
    // edge: relu(E @ W1a_bot + P[src]) scatter-added into S[dst]; deg counts
    gnn_gemm<<<GRID, 256, SMEM_REQ>>>(edgef, W1a + F * F, nullptr, nullptr, nullptr, nullptr,
                                      src, dst, NE, edgeTiles, 0, 1);
    // H = S @ W1b + deg*b1b + node
    gnn_gemm<<<GRID, 256, SMEM_REQ>>>(S, W1b, b1b, deg, node, H,
                                      nullptr, nullptr, NN, nodeTiles, 0, 0);
    // T = relu(H @ W2a + b2a)
    gnn_gemm<<<GRID, 256, SMEM_REQ>>>(H, W2a, b2a, nullptr, nullptr, T,
                                      nullptr, nullptr, NN, nodeTiles, 1, 0);
    // out = T @ W2b + b2b
    gnn_gemm<<<GRID, 256, SMEM_REQ>>>(T, W2b, b2b, nullptr, nullptr, out,
                                      nullptr, nullptr, NN, nodeTiles, 0, 0);
}

// round 4
// speedup vs baseline: 2.9145x; 1.3219x over previous
#include <cuda_runtime.h>
#include <cuda_bf16.h>
#include <cstdint>

#define F 128
#define NN 50000
#define NE 800000

#define LDA 136            // bf16 elems per smem row (pad: conflict-free ldmatrix)
#define LDC 132            // fp32 elems per Cs row

// ---- smem layout (bytes) ----
#define OFF_WHI 0u
#define OFF_WLO 34816u     // 128*136*2
#define OFF_SA  69632u     // split A hi; lo at +34816; Cs (128*132*4=67584) aliases this region
#define OFF_RAW 139264u    // raw fp32 A tile, 65536 B
#define SMEM_REQ 204800u

// ---------------- persistent device scratch ----------------
__device__ float g_P[(size_t)NN * F];
__device__ float g_S[(size_t)NN * F];
__device__ float g_H[(size_t)NN * F];
__device__ float g_T[(size_t)NN * F];
__device__ float g_deg[NN];

// ---------------- low-level helpers ----------------
__device__ __forceinline__ uint32_t cvta_smem(const void* p) {
    uint32_t a;
    asm("{ .reg .u64 t; cvta.to.shared.u64 t, %1; cvt.u32.u64 %0, t; }" : "=r"(a) : "l"(p));
    return a;
}

__device__ __forceinline__ void ldsm4(uint32_t addr, uint32_t& r0, uint32_t& r1,
                                      uint32_t& r2, uint32_t& r3) {
    asm volatile("ldmatrix.sync.aligned.m8n8.x4.shared.b16 {%0,%1,%2,%3}, [%4];"
                 : "=r"(r0), "=r"(r1), "=r"(r2), "=r"(r3) : "r"(addr));
}

__device__ __forceinline__ void mma_bf16(float* c, uint32_t a0, uint32_t a1, uint32_t a2,
                                         uint32_t a3, uint32_t b0, uint32_t b1) {
    asm volatile("mma.sync.aligned.m16n8k16.row.col.f32.bf16.bf16.f32 "
                 "{%0,%1,%2,%3}, {%4,%5,%6,%7}, {%8,%9}, {%0,%1,%2,%3};"
                 : "+f"(c[0]), "+f"(c[1]), "+f"(c[2]), "+f"(c[3])
                 : "r"(a0), "r"(a1), "r"(a2), "r"(a3), "r"(b0), "r"(b1));
}

__device__ __forceinline__ void splitf(float x, __nv_bfloat16* hi, __nv_bfloat16* lo) {
    __nv_bfloat16 h = __float2bfloat16(x);
    *hi = h;
    *lo = __float2bfloat16(x - __bfloat162float(h));
}

__device__ __forceinline__ void cp16(uint32_t dst, const float* src) {
    asm volatile("cp.async.cg.shared.global [%0], [%1], 16;" :: "r"(dst), "l"(src) : "memory");
}
__device__ __forceinline__ void cp_commit() { asm volatile("cp.async.commit_group;" ::: "memory"); }
__device__ __forceinline__ void cp_wait0()  { asm volatile("cp.async.wait_group 0;"  ::: "memory"); }

__global__ void zero_kernel() {
    size_t stride = (size_t)gridDim.x * blockDim.x;
    size_t gid = (size_t)blockIdx.x * blockDim.x + threadIdx.x;
    float4 z = make_float4(0.f, 0.f, 0.f, 0.f);
    float4* S4 = reinterpret_cast<float4*>(g_S);
    for (size_t i = gid; i < (size_t)NN * F / 4; i += stride) S4[i] = z;
    for (size_t i = gid; i < (size_t)NN; i += stride) g_deg[i] = 0.f;
}

// ---------------- persistent fused GEMM ----------------
__global__ void __launch_bounds__(512, 1)
gnn_gemm(const float* __restrict__ A, const float* __restrict__ Wg,
         const float* __restrict__ bias, const float* __restrict__ rowscale,
         const float* __restrict__ residual, float* __restrict__ outp,
         const int* __restrict__ src, const int* __restrict__ dst,
         int M, int ntiles, int do_relu, int is_edge) {
    extern __shared__ char sm[];
    const uint32_t sb = cvta_smem(sm);
    const int tid = threadIdx.x;

    // ---- stage weights once: B^T[n][k] = Wg[k][n], split hi/lo ----
    {
        const float4* W4 = reinterpret_cast<const float4*>(Wg);
        for (int idx = tid; idx < F * F / 4; idx += 512) {
            int k = idx >> 5;
            int n0 = (idx & 31) << 2;
            float4 wv = __ldg(W4 + idx);
#pragma unroll
            for (int j = 0; j < 4; j++) {
                __nv_bfloat16 h, l;
                splitf((&wv.x)[j], &h, &l);
                uint32_t o = (uint32_t)((n0 + j) * LDA + k) * 2u;
                *reinterpret_cast<__nv_bfloat16*>(sm + OFF_WHI + o) = h;
                *reinterpret_cast<__nv_bfloat16*>(sm + OFF_WLO + o) = l;
            }
        }
    }

    const int w = tid >> 5, lane = tid & 31;
    const int wr = w >> 2, wc = w & 3;          // warp tile: rows wr*32.., cols wc*32..
    const int g = lane >> 2, t4 = lane & 3;

    const uint32_t uA = (uint32_t)((wr * 32 + ((lane >> 3) & 1) * 8 + (lane & 7)) * LDA
                                   + (lane >> 4) * 8);
    const uint32_t uB = (uint32_t)((wc * 32 + (lane >> 4) * 8 + (lane & 7)) * LDA
                                   + ((lane >> 3) & 1) * 8);

    float* Cs = reinterpret_cast<float*>(sm + OFF_SA);   // aliases split-A region

    // ---- pipeline helpers (macro-free inline lambdas) ----
    auto fetch_raw = [&](int row0) {
#pragma unroll
        for (int i = 0; i < 8; i++) {
            int idx = tid + i * 512;
            int r = idx >> 5, c = (idx & 31) << 2;
            int gr = row0 + r;
            if (gr < M) cp16(sb + OFF_RAW + (uint32_t)idx * 16u, A + (size_t)gr * F + c);
            else *reinterpret_cast<float4*>(sm + OFF_RAW + idx * 16) = make_float4(0.f, 0.f, 0.f, 0.f);
        }
        cp_commit();
    };
    auto split_raw = [&]() {
#pragma unroll
        for (int i = 0; i < 8; i++) {
            int idx = tid + i * 512;
            int r = idx >> 5, c4 = (idx & 31) << 2;
            float4 v = *reinterpret_cast<const float4*>(sm + OFF_RAW + idx * 16);
            __nv_bfloat16 h0, l0, h1, l1, h2, l2, h3, l3;
            splitf(v.x, &h0, &l0); splitf(v.y, &h1, &l1);
            splitf(v.z, &h2, &l2); splitf(v.w, &h3, &l3);
            uint32_t o = (uint32_t)(r * LDA + c4) * 2u;
            __nv_bfloat162 p0; p0.x = h0; p0.y = h1;
            __nv_bfloat162 p1; p1.x = h2; p1.y = h3;
            __nv_bfloat162 q0; q0.x = l0; q0.y = l1;
            __nv_bfloat162 q1; q1.x = l2; q1.y = l3;
            *reinterpret_cast<__nv_bfloat162*>(sm + OFF_SA + o)              = p0;
            *reinterpret_cast<__nv_bfloat162*>(sm + OFF_SA + o + 4)          = p1;
            *reinterpret_cast<__nv_bfloat162*>(sm + OFF_SA + 34816u + o)     = q0;
            *reinterpret_cast<__nv_bfloat162*>(sm + OFF_SA + 34816u + o + 4) = q1;
        }
    };

    int tile = blockIdx.x;
    if (tile < ntiles) {
        // prologue: raw <- tile0; split; raw <- tile1 (in flight)
        fetch_raw(tile * 128);
        cp_wait0(); __syncthreads();        // also covers weight staging
        split_raw(); __syncthreads();
        int next = tile + gridDim.x;
        if (next < ntiles) fetch_raw(next * 128);

        for (;;) {
            const int row0 = tile * 128;

            // ---- 128x128x128 bf16x3 MMA on split buffers ----
            float acc[2][4][4];
#pragma unroll
            for (int mt = 0; mt < 2; mt++)
#pragma unroll
                for (int nt = 0; nt < 4; nt++)
#pragma unroll
                    for (int i = 0; i < 4; i++) acc[mt][nt][i] = 0.f;

#pragma unroll
            for (int ks = 0; ks < 8; ks++) {
                const uint32_t kofs = (uint32_t)(ks * 16) * 2u;
                uint32_t ah[2][4], al[2][4];
#pragma unroll
                for (int mt = 0; mt < 2; mt++) {
                    uint32_t ao = (uA + (uint32_t)(mt * 16 * LDA)) * 2u + kofs;
                    ldsm4(sb + OFF_SA + ao, ah[mt][0], ah[mt][1], ah[mt][2], ah[mt][3]);
                    ldsm4(sb + OFF_SA + 34816u + ao, al[mt][0], al[mt][1], al[mt][2], al[mt][3]);
                }
                uint32_t bh[4][2], bl[4][2];
#pragma unroll
                for (int np = 0; np < 2; np++) {
                    uint32_t bo = (uB + (uint32_t)(np * 16 * LDA)) * 2u + kofs;
                    ldsm4(sb + OFF_WHI + bo, bh[2*np][0], bh[2*np][1], bh[2*np+1][0], bh[2*np+1][1]);
                    ldsm4(sb + OFF_WLO + bo, bl[2*np][0], bl[2*np][1], bl[2*np+1][0], bl[2*np+1][1]);
                }
#pragma unroll
                for (int mt = 0; mt < 2; mt++)
#pragma unroll
                    for (int nt = 0; nt < 4; nt++) {
                        mma_bf16(acc[mt][nt], ah[mt][0], ah[mt][1], ah[mt][2], ah[mt][3],
                                 bh[nt][0], bh[nt][1]);
                        mma_bf16(acc[mt][nt], al[mt][0], al[mt][1], al[mt][2], al[mt][3],
                                 bh[nt][0], bh[nt][1]);
                        mma_bf16(acc[mt][nt], ah[mt][0], ah[mt][1], ah[mt][2], ah[mt][3],
                                 bl[nt][0], bl[nt][1]);
                    }
            }
            __syncthreads();   // split-A reads done; region becomes Cs

            // ---- spill acc -> Cs ----
#pragma unroll
            for (int mt = 0; mt < 2; mt++) {
                const int r0 = wr * 32 + mt * 16 + g;
#pragma unroll
                for (int nt = 0; nt < 4; nt++) {
                    const int c0 = wc * 32 + nt * 8 + 2 * t4;
                    *reinterpret_cast<float2*>(Cs + r0 * LDC + c0) =
                        make_float2(acc[mt][nt][0], acc[mt][nt][1]);
                    *reinterpret_cast<float2*>(Cs + (r0 + 8) * LDC + c0) =
                        make_float2(acc[mt][nt][2], acc[mt][nt][3]);
                }
            }
            __syncthreads();

            // ---- epilogue ----
            if (is_edge) {
                for (int idx = tid; idx < 4096; idx += 512) {
                    int r = idx >> 5;
                    int c = (idx & 31) << 2;
                    int e = row0 + r;
                    int s = __ldg(src + e);
                    int d = __ldg(dst + e);
                    float4 v = *reinterpret_cast<float4*>(Cs + r * LDC + c);
                    float4 p = __ldg(reinterpret_cast<const float4*>(g_P + (size_t)s * F + c));
                    v.x = fmaxf(v.x + p.x, 0.f);
                    v.y = fmaxf(v.y + p.y, 0.f);
                    v.z = fmaxf(v.z + p.z, 0.f);
                    v.w = fmaxf(v.w + p.w, 0.f);
                    float* addr = g_S + (size_t)d * F + c;
                    asm volatile("red.global.add.v4.f32 [%0], {%1,%2,%3,%4};"
                                 :: "l"(addr), "f"(v.x), "f"(v.y), "f"(v.z), "f"(v.w)
                                 : "memory");
                }
                if (tid < 128) atomicAdd(&g_deg[__ldg(dst + row0 + tid)], 1.0f);
            } else {
                for (int idx = tid; idx < 4096; idx += 512) {
                    int r = idx >> 5;
                    int c = (idx & 31) << 2;
                    int gr = row0 + r;
                    if (gr >= M) continue;
                    float4 v = *reinterpret_cast<float4*>(Cs + r * LDC + c);
                    float4 bb = __ldg(reinterpret_cast<const float4*>(bias + c));
                    float rs = rowscale ? __ldg(rowscale + gr) : 1.f;
                    v.x += rs * bb.x; v.y += rs * bb.y; v.z += rs * bb.z; v.w += rs * bb.w;
                    if (residual) {
                        float4 q = __ldg(reinterpret_cast<const float4*>(residual + (size_t)gr * F + c));
                        v.x += q.x; v.y += q.y; v.z += q.z; v.w += q.w;
                    }
                    if (do_relu) {
                        v.x = fmaxf(v.x, 0.f); v.y = fmaxf(v.y, 0.f);
                        v.z = fmaxf(v.z, 0.f); v.w = fmaxf(v.w, 0.f);
                    }
                    *reinterpret_cast<float4*>(outp + (size_t)gr * F + c) = v;
                }
            }
            __syncthreads();   // Cs reads done; split-A region writable

            if (next >= ntiles) break;
            // raw[next] has been in flight during MMA+epilogue
            cp_wait0(); __syncthreads();
            split_raw(); __syncthreads();
            tile = next; next += gridDim.x;
            if (next < ntiles) fetch_raw(next * 128);
        }
    }
}

// ---------------- launch ----------------
extern "C" void kernel_launch(void* const* d_in, const int* in_sizes, int n_in,
                              void* d_out, int out_size) {
    const float* node  = (const float*)d_in[0];
    const float* edgef = (const float*)d_in[1];
    const int*   src   = (const int*)  d_in[2];
    const int*   dst   = (const int*)  d_in[3];
    const float* W1a   = (const float*)d_in[4];
    const float* b1a   = (const float*)d_in[5];
    const float* W1b   = (const float*)d_in[6];
    const float* b1b   = (const float*)d_in[7];
    const float* W2a   = (const float*)d_in[8];
    const float* b2a   = (const float*)d_in[9];
    const float* W2b   = (const float*)d_in[10];
    const float* b2b   = (const float*)d_in[11];
    float* out = (float*)d_out;

    cudaFuncSetAttribute(gnn_gemm, cudaFuncAttributeMaxDynamicSharedMemorySize, (int)SMEM_REQ);

    float *P, *S, *H, *T, *deg;
    cudaGetSymbolAddress((void**)&P,   g_P);
    cudaGetSymbolAddress((void**)&S,   g_S);
    cudaGetSymbolAddress((void**)&H,   g_H);
    cudaGetSymbolAddress((void**)&T,   g_T);
    cudaGetSymbolAddress((void**)&deg, g_deg);

    const int nodeTiles = (NN + 127) / 128;   // 391
    const int edgeTiles = NE / 128;           // 6250
    const int GRID = 148;

    zero_kernel<<<512, 256>>>();
    // P = node @ W1a_top + b1a
    gnn_gemm<<<GRID, 512, SMEM_REQ>>>(node, W1a, b1a, nullptr, nullptr, P,
                                      nullptr, nullptr, NN, nodeTiles, 0, 0);
    // edge: relu(E @ W1a_bot + P[src]) scatter-added into S[dst]; deg counts
    gnn_gemm<<<GRID, 512, SMEM_REQ>>>(edgef, W1a + F * F, nullptr, nullptr, nullptr, nullptr,
                                      src, dst, NE, edgeTiles, 0, 1);
    // H = S @ W1b + deg*b1b + node
    gnn_gemm<<<GRID, 512, SMEM_REQ>>>(S, W1b, b1b, deg, node, H,
                                      nullptr, nullptr, NN, nodeTiles, 0, 0);
    // T = relu(H @ W2a + b2a)
    gnn_gemm<<<GRID, 512, SMEM_REQ>>>(H, W2a, b2a, nullptr, nullptr, T,
                                      nullptr, nullptr, NN, nodeTiles, 1, 0);
    // out = T @ W2b + b2b
    gnn_gemm<<<GRID, 512, SMEM_REQ>>>(T, W2b, b2b, nullptr, nullptr, out,
                                      nullptr, nullptr, NN, nodeTiles, 0, 0);
}